// round 2
// baseline (speedup 1.0000x reference)
#include <cuda_runtime.h>
#include <cstddef>

#define BB 64
#define NN 2048
#define II 16
#define JJ 32
#define OO 32
#define JO 1024      // J*O
#define NCHUNK 16
#define CHUNK 128    // NN / NCHUNK
#define NB 8         // n's per barrier round in pass_kernel (== #warps)

// Scratch (allocation-free rule: __device__ globals).
// g_pred: 512 MB fp32 predictions [B][N][JO]
__device__ float g_pred[(size_t)BB * NN * JO];
// per-chunk partial s sums [NCHUNK][B][JO] (fully overwritten every pass -> no zeroing needed)
__device__ float g_partial[(size_t)NCHUNK * BB * JO];
// v after squash [B][JO]
__device__ float g_v[BB * JO];
// routing logits b [B][N][J] (written in pass mode 1, read in mode 2)
__device__ float g_blog[(size_t)BB * NN * JJ];

// ---------------------------------------------------------------------------
// K1: predictions. One CTA per n. 256 threads; thread t owns jo in [4t, 4t+4).
// W rows for those jo live in 64 registers (coalesced 256B/thread GMEM read),
// x tile [64][16] in smem (broadcast reads in the b-loop).
// ---------------------------------------------------------------------------
__global__ __launch_bounds__(256, 2)
void pred_kernel(const float* __restrict__ x, const float* __restrict__ w) {
    const int n = blockIdx.x;
    const int t = threadIdx.x;

    __shared__ float4 x_s[BB][4];
    {
        int b = t >> 2, q = t & 3;
        x_s[b][q] = reinterpret_cast<const float4*>(x + ((size_t)b * NN + n) * II)[q];
    }

    float wreg[4][16];
    const float4* wp = reinterpret_cast<const float4*>(w + ((size_t)n * JO + 4 * t) * II);
#pragma unroll
    for (int q = 0; q < 4; ++q) {
#pragma unroll
        for (int c = 0; c < 4; ++c) {
            float4 f = wp[q * 4 + c];
            wreg[q][4 * c + 0] = f.x; wreg[q][4 * c + 1] = f.y;
            wreg[q][4 * c + 2] = f.z; wreg[q][4 * c + 3] = f.w;
        }
    }
    __syncthreads();

    float4* outp = reinterpret_cast<float4*>(g_pred + (size_t)n * JO + 4 * t);
#pragma unroll 4
    for (int b = 0; b < BB; ++b) {
        float xr[16];
#pragma unroll
        for (int q = 0; q < 4; ++q) {
            float4 f = x_s[b][q];
            xr[4 * q + 0] = f.x; xr[4 * q + 1] = f.y;
            xr[4 * q + 2] = f.z; xr[4 * q + 3] = f.w;
        }
        float a0 = 0.f, a1 = 0.f, a2 = 0.f, a3 = 0.f;
#pragma unroll
        for (int i = 0; i < 16; ++i) {
            a0 = fmaf(xr[i], wreg[0][i], a0);
            a1 = fmaf(xr[i], wreg[1][i], a1);
            a2 = fmaf(xr[i], wreg[2][i], a2);
            a3 = fmaf(xr[i], wreg[3][i], a3);
        }
        outp[(size_t)b * (NN * JO / 4)] = make_float4(a0, a1, a2, a3);
    }
}

// ---------------------------------------------------------------------------
// Routing pass. Grid (NCHUNK, B). 256 threads; thread t owns pred quad jo
// [4t,4t+4) (j = t>>3). mode 0: c uniform 1/32 (iter 0 s). mode 1: a = pred.v,
// b_log = a, c = softmax(a), accumulate s. mode 2: a += old b_log, softmax, s.
// s accumulated in per-thread float4 registers -> deterministic, no atomics.
// ---------------------------------------------------------------------------
__global__ __launch_bounds__(256)
void pass_kernel(int mode) {
    const int chunk = blockIdx.x;
    const int b = blockIdx.y;
    const int t = threadIdx.x;
    const int warp = t >> 5;
    const int lane = t & 31;
    const int j = t >> 3;          // capsule index of this thread's quad

    __shared__ float a_buf[NB][JJ];
    __shared__ float c_buf[NB][JJ];

    float4 vv = make_float4(0.f, 0.f, 0.f, 0.f);
    if (mode > 0) vv = reinterpret_cast<const float4*>(g_v + b * JO)[t];

    float4 sacc = make_float4(0.f, 0.f, 0.f, 0.f);
    const float4* predp = reinterpret_cast<const float4*>(
        g_pred + ((size_t)b * NN + (size_t)chunk * CHUNK) * JO);

    for (int n0 = 0; n0 < CHUNK; n0 += NB) {
        float4 p[NB];
#pragma unroll
        for (int k = 0; k < NB; ++k)
            p[k] = predp[(size_t)(n0 + k) * (JO / 4) + t];

        if (mode > 0) {
#pragma unroll
            for (int k = 0; k < NB; ++k) {
                float d = p[k].x * vv.x + p[k].y * vv.y + p[k].z * vv.z + p[k].w * vv.w;
                d += __shfl_xor_sync(0xffffffffu, d, 1);
                d += __shfl_xor_sync(0xffffffffu, d, 2);
                d += __shfl_xor_sync(0xffffffffu, d, 4);
                if ((lane & 7) == 0) a_buf[k][j] = d;
            }
            __syncthreads();
            {   // each of the 8 warps runs softmax for one n
                const int k = warp;
                const int n = chunk * CHUNK + n0 + k;
                float a = a_buf[k][lane];
                size_t bidx = ((size_t)b * NN + n) * JJ + lane;
                if (mode == 2) a += g_blog[bidx];
                else           g_blog[bidx] = a;   // mode 1: b1 = agreement (b0 = 0)
                float m = a;
#pragma unroll
                for (int s = 16; s > 0; s >>= 1)
                    m = fmaxf(m, __shfl_xor_sync(0xffffffffu, m, s));
                float e = __expf(a - m);
                float ssum = e;
#pragma unroll
                for (int s = 16; s > 0; s >>= 1)
                    ssum += __shfl_xor_sync(0xffffffffu, ssum, s);
                c_buf[k][lane] = e / ssum;
            }
            __syncthreads();
#pragma unroll
            for (int k = 0; k < NB; ++k) {
                float c = c_buf[k][j];
                sacc.x = fmaf(c, p[k].x, sacc.x);
                sacc.y = fmaf(c, p[k].y, sacc.y);
                sacc.z = fmaf(c, p[k].z, sacc.z);
                sacc.w = fmaf(c, p[k].w, sacc.w);
            }
        } else {
#pragma unroll
            for (int k = 0; k < NB; ++k) {
                sacc.x += p[k].x; sacc.y += p[k].y;
                sacc.z += p[k].z; sacc.w += p[k].w;
            }
        }
    }
    if (mode == 0) {
        const float inv = 1.0f / 32.0f;
        sacc.x *= inv; sacc.y *= inv; sacc.z *= inv; sacc.w *= inv;
    }
    reinterpret_cast<float4*>(g_partial + ((size_t)chunk * BB + b) * JO)[t] = sacc;
}

// ---------------------------------------------------------------------------
// Reduce the NCHUNK partials and squash. One block per b, thread t = jo,
// warp = capsule j. Writes g_v; final call also writes d_out.
// ---------------------------------------------------------------------------
__global__ __launch_bounds__(1024)
void squash_kernel(float* out) {
    const int b = blockIdx.x;
    const int t = threadIdx.x;   // jo index
    float s = 0.f;
#pragma unroll
    for (int k = 0; k < NCHUNK; ++k)
        s += g_partial[((size_t)k * BB + b) * JO + t];
    float sq = s * s;
#pragma unroll
    for (int m = 16; m > 0; m >>= 1)
        sq += __shfl_xor_sync(0xffffffffu, sq, m);
    float scale = (sq / (1.0f + sq)) * rsqrtf(sq + 1e-8f);
    float v = s * scale;
    g_v[b * JO + t] = v;
    if (out) out[b * JO + t] = v;
}

// ---------------------------------------------------------------------------
extern "C" void kernel_launch(void* const* d_in, const int* in_sizes, int n_in,
                              void* d_out, int out_size) {
    const float* x = (const float*)d_in[0];   // [64, 2048, 16] f32
    const float* w = (const float*)d_in[1];   // [2048, 32, 32, 16] f32
    float* out = (float*)d_out;               // [64, 32, 32] f32

    pred_kernel<<<NN, 256>>>(x, w);
    dim3 pg(NCHUNK, BB);
    pass_kernel<<<pg, 256>>>(0);              // iter 0: uniform c -> s0
    squash_kernel<<<BB, 1024>>>(nullptr);     // v0
    pass_kernel<<<pg, 256>>>(1);              // a0 -> b1 -> c1 -> s1
    squash_kernel<<<BB, 1024>>>(nullptr);     // v1
    pass_kernel<<<pg, 256>>>(2);              // a1 -> b2 -> c2 -> s2
    squash_kernel<<<BB, 1024>>>(out);         // v2 -> output
}

// round 4
// speedup vs baseline: 1.2537x; 1.2537x over previous
#include <cuda_runtime.h>
#include <cuda_fp16.h>
#include <cstddef>
#include <cstdint>

#define BB 64
#define NN 2048
#define II 16
#define JJ 32
#define OO 32
#define JO 1024      // J*O
#define NCHUNK 16
#define CHUNK 128    // NN / NCHUNK
#define NB 8         // n's per barrier round in pass_kernel (== #warps)

// Scratch (allocation-free rule: __device__ globals).
// g_predh: 256 MB fp16 predictions [B][N][JO]
__device__ __half g_predh[(size_t)BB * NN * JO];
// per-chunk partial s sums [NCHUNK][B][JO] (fully overwritten every pass)
__device__ float g_partial[(size_t)NCHUNK * BB * JO];
// v after squash [B][JO]
__device__ float g_v[BB * JO];
// routing logits b [B][N][J] (written in pass mode 1, read in mode 2)
__device__ float g_blog[(size_t)BB * NN * JJ];

// ---- packed fp32x2 helpers (sm_103a) --------------------------------------
__device__ __forceinline__ unsigned long long pk2(float a, float b) {
    unsigned long long r;
    asm("mov.b64 %0, {%1, %2};" : "=l"(r) : "f"(a), "f"(b));
    return r;
}
__device__ __forceinline__ void ffma2(unsigned long long& d,
                                      unsigned long long a,
                                      unsigned long long b) {
    asm("fma.rn.f32x2 %0, %1, %2, %0;" : "+l"(d) : "l"(a), "l"(b));
}
__device__ __forceinline__ float2 up2(unsigned long long v) {
    float2 f;
    asm("mov.b64 {%0, %1}, %2;" : "=f"(f.x), "=f"(f.y) : "l"(v));
    return f;
}
__device__ __forceinline__ float4 h4_to_f4(uint2 u) {
    __half2 h0 = *reinterpret_cast<__half2*>(&u.x);
    __half2 h1 = *reinterpret_cast<__half2*>(&u.y);
    float2 a = __half22float2(h0);
    float2 c = __half22float2(h1);
    return make_float4(a.x, a.y, c.x, c.y);
}

// ---------------------------------------------------------------------------
// K1: predictions via packed f32x2 FFMA. One CTA per n, 256 threads; thread t
// owns jo in [4t,4t+4). Weight pairs (w_jo0[i],w_jo1[i]) packed once into
// 64-bit regs; x stored duplicated (x,x) in smem and loaded straight into
// 64-bit register pairs via ld.shared.v2.u64 (broadcast, conflict-free).
// Per b: 8 LDS.128 + 32 FFMA2 instead of 64 FFMA. Output fp16.
// ---------------------------------------------------------------------------
__global__ __launch_bounds__(256, 2)
void pred_kernel(const float* __restrict__ x, const float* __restrict__ w) {
    const int n = blockIdx.x;
    const int t = threadIdx.x;

    __shared__ float2 xs2[BB][II];   // (x,x) duplicated pairs, 8 KB
    {
        int b = t >> 2, q = t & 3;
        float4 f = reinterpret_cast<const float4*>(x + ((size_t)b * NN + n) * II)[q];
        xs2[b][4 * q + 0] = make_float2(f.x, f.x);
        xs2[b][4 * q + 1] = make_float2(f.y, f.y);
        xs2[b][4 * q + 2] = make_float2(f.z, f.z);
        xs2[b][4 * q + 3] = make_float2(f.w, f.w);
    }

    float wr[4][16];
    const float4* wp = reinterpret_cast<const float4*>(w + ((size_t)n * JO + 4 * t) * II);
#pragma unroll
    for (int q = 0; q < 4; ++q) {
#pragma unroll
        for (int c = 0; c < 4; ++c) {
            float4 f = wp[q * 4 + c];
            wr[q][4 * c + 0] = f.x; wr[q][4 * c + 1] = f.y;
            wr[q][4 * c + 2] = f.z; wr[q][4 * c + 3] = f.w;
        }
    }
    unsigned long long wp01[16], wp23[16];
#pragma unroll
    for (int i = 0; i < 16; ++i) {
        wp01[i] = pk2(wr[0][i], wr[1][i]);
        wp23[i] = pk2(wr[2][i], wr[3][i]);
    }
    __syncthreads();

    __half* outp = g_predh + (size_t)n * JO + 4 * t;
    uint32_t xbase = (uint32_t)__cvta_generic_to_shared(&xs2[0][0]);

#pragma unroll 4
    for (int b = 0; b < BB; ++b) {
        uint32_t xa = xbase + b * (II * 8);
        unsigned long long acc01 = 0ull, acc23 = 0ull;  // bits of (0.f,0.f)
#pragma unroll
        for (int k = 0; k < 8; ++k) {
            unsigned long long xx0, xx1;
            asm("ld.shared.v2.u64 {%0, %1}, [%2];"
                : "=l"(xx0), "=l"(xx1) : "r"(xa + k * 16));
            ffma2(acc01, xx0, wp01[2 * k]);
            ffma2(acc23, xx0, wp23[2 * k]);
            ffma2(acc01, xx1, wp01[2 * k + 1]);
            ffma2(acc23, xx1, wp23[2 * k + 1]);
        }
        float2 a01 = up2(acc01);
        float2 a23 = up2(acc23);
        __half2 b01 = __float22half2_rn(a01);
        __half2 b23 = __float22half2_rn(a23);
        uint2 st;
        st.x = *reinterpret_cast<unsigned int*>(&b01);
        st.y = *reinterpret_cast<unsigned int*>(&b23);
        *reinterpret_cast<uint2*>(outp + (size_t)b * NN * JO) = st;
    }
}

// ---------------------------------------------------------------------------
// Routing pass over fp16 predictions. Grid (NCHUNK, B). 256 threads; thread t
// owns pred quad jo [4t,4t+4) (j = t>>3). mode 0: uniform c. mode 1: a=pred.v,
// blog=a, softmax, s. mode 2: a = blog + pred.v, softmax, s.
// ---------------------------------------------------------------------------
__global__ __launch_bounds__(256)
void pass_kernel(int mode) {
    const int chunk = blockIdx.x;
    const int b = blockIdx.y;
    const int t = threadIdx.x;
    const int warp = t >> 5;
    const int lane = t & 31;
    const int j = t >> 3;

    __shared__ float a_buf[NB][JJ];
    __shared__ float c_buf[NB][JJ];

    float4 vv = make_float4(0.f, 0.f, 0.f, 0.f);
    if (mode > 0) vv = reinterpret_cast<const float4*>(g_v + b * JO)[t];

    float4 sacc = make_float4(0.f, 0.f, 0.f, 0.f);
    const uint2* predp = reinterpret_cast<const uint2*>(
        g_predh + ((size_t)b * NN + (size_t)chunk * CHUNK) * JO);

    for (int n0 = 0; n0 < CHUNK; n0 += NB) {
        float4 p[NB];
#pragma unroll
        for (int k = 0; k < NB; ++k)
            p[k] = h4_to_f4(predp[(size_t)(n0 + k) * (JO / 4) + t]);

        if (mode > 0) {
#pragma unroll
            for (int k = 0; k < NB; ++k) {
                float d = p[k].x * vv.x + p[k].y * vv.y + p[k].z * vv.z + p[k].w * vv.w;
                d += __shfl_xor_sync(0xffffffffu, d, 1);
                d += __shfl_xor_sync(0xffffffffu, d, 2);
                d += __shfl_xor_sync(0xffffffffu, d, 4);
                if ((lane & 7) == 0) a_buf[k][j] = d;
            }
            __syncthreads();
            {   // each of the 8 warps runs softmax for one n
                const int k = warp;
                const int n = chunk * CHUNK + n0 + k;
                float a = a_buf[k][lane];
                size_t bidx = ((size_t)b * NN + n) * JJ + lane;
                if (mode == 2) a += g_blog[bidx];
                else           g_blog[bidx] = a;   // mode 1: b1 = agreement (b0 = 0)
                float m = a;
#pragma unroll
                for (int s = 16; s > 0; s >>= 1)
                    m = fmaxf(m, __shfl_xor_sync(0xffffffffu, m, s));
                float e = __expf(a - m);
                float ssum = e;
#pragma unroll
                for (int s = 16; s > 0; s >>= 1)
                    ssum += __shfl_xor_sync(0xffffffffu, ssum, s);
                c_buf[k][lane] = e / ssum;
            }
            __syncthreads();
#pragma unroll
            for (int k = 0; k < NB; ++k) {
                float c = c_buf[k][j];
                sacc.x = fmaf(c, p[k].x, sacc.x);
                sacc.y = fmaf(c, p[k].y, sacc.y);
                sacc.z = fmaf(c, p[k].z, sacc.z);
                sacc.w = fmaf(c, p[k].w, sacc.w);
            }
        } else {
#pragma unroll
            for (int k = 0; k < NB; ++k) {
                sacc.x += p[k].x; sacc.y += p[k].y;
                sacc.z += p[k].z; sacc.w += p[k].w;
            }
        }
    }
    if (mode == 0) {
        const float inv = 1.0f / 32.0f;
        sacc.x *= inv; sacc.y *= inv; sacc.z *= inv; sacc.w *= inv;
    }
    reinterpret_cast<float4*>(g_partial + ((size_t)chunk * BB + b) * JO)[t] = sacc;
}

// ---------------------------------------------------------------------------
// Reduce the NCHUNK partials and squash. One block per b, thread t = jo,
// warp = capsule j. Writes g_v; final call also writes d_out.
// ---------------------------------------------------------------------------
__global__ __launch_bounds__(1024)
void squash_kernel(float* out) {
    const int b = blockIdx.x;
    const int t = threadIdx.x;
    float s = 0.f;
#pragma unroll
    for (int k = 0; k < NCHUNK; ++k)
        s += g_partial[((size_t)k * BB + b) * JO + t];
    float sq = s * s;
#pragma unroll
    for (int m = 16; m > 0; m >>= 1)
        sq += __shfl_xor_sync(0xffffffffu, sq, m);
    float scale = (sq / (1.0f + sq)) * rsqrtf(sq + 1e-8f);
    float v = s * scale;
    g_v[b * JO + t] = v;
    if (out) out[b * JO + t] = v;
}

// ---------------------------------------------------------------------------
extern "C" void kernel_launch(void* const* d_in, const int* in_sizes, int n_in,
                              void* d_out, int out_size) {
    const float* x = (const float*)d_in[0];   // [64, 2048, 16] f32
    const float* w = (const float*)d_in[1];   // [2048, 32, 32, 16] f32
    float* out = (float*)d_out;               // [64, 32, 32] f32

    pred_kernel<<<NN, 256>>>(x, w);
    dim3 pg(NCHUNK, BB);
    pass_kernel<<<pg, 256>>>(0);              // iter 0: uniform c -> s0
    squash_kernel<<<BB, 1024>>>(nullptr);     // v0
    pass_kernel<<<pg, 256>>>(1);              // a0 -> b1 -> c1 -> s1
    squash_kernel<<<BB, 1024>>>(nullptr);     // v1
    pass_kernel<<<pg, 256>>>(2);              // a1 -> b2 -> c2 -> s2
    squash_kernel<<<BB, 1024>>>(out);         // v2 -> output
}

// round 5
// speedup vs baseline: 1.3154x; 1.0492x over previous
#include <cuda_runtime.h>
#include <cuda_fp16.h>
#include <cstddef>
#include <cstdint>

#define BB 64
#define NN 2048
#define II 16
#define JJ 32
#define OO 32
#define JO 1024      // J*O
#define NCHUNK 16
#define CHUNK 128    // NN / NCHUNK
#define NB 8         // n's per barrier round in pass_kernel (== #warps)

// Scratch (allocation-free rule: __device__ globals).
__device__ __half g_predh[(size_t)BB * NN * JO];               // 256 MB fp16 predictions
__device__ float g_partial[(size_t)NCHUNK * BB * JO];          // per-chunk partial s sums
__device__ float g_blog[(size_t)BB * NN * JJ];                 // routing logits (pass1 -> pass2)

// ---- packed fp32x2 helpers (sm_103a) --------------------------------------
__device__ __forceinline__ unsigned long long pk2(float a, float b) {
    unsigned long long r;
    asm("mov.b64 %0, {%1, %2};" : "=l"(r) : "f"(a), "f"(b));
    return r;
}
__device__ __forceinline__ void ffma2(unsigned long long& d,
                                      unsigned long long a,
                                      unsigned long long b) {
    asm("fma.rn.f32x2 %0, %1, %2, %0;" : "+l"(d) : "l"(a), "l"(b));
}
__device__ __forceinline__ float2 up2(unsigned long long v) {
    float2 f;
    asm("mov.b64 {%0, %1}, %2;" : "=f"(f.x), "=f"(f.y) : "l"(v));
    return f;
}
__device__ __forceinline__ float4 h4_to_f4(uint2 u) {
    __half2 h0 = *reinterpret_cast<__half2*>(&u.x);
    __half2 h1 = *reinterpret_cast<__half2*>(&u.y);
    float2 a = __half22float2(h0);
    float2 c = __half22float2(h1);
    return make_float4(a.x, a.y, c.x, c.y);
}

// ---------------------------------------------------------------------------
// K1: predictions via packed f32x2 FFMA. One CTA per n, 256 threads; thread t
// owns jo in [4t,4t+4). Weight pairs packed once into 64-bit regs; x stored
// duplicated (x,x) in smem and loaded as 64-bit pairs (broadcast LDS.128).
// Output fp16.
// ---------------------------------------------------------------------------
__global__ __launch_bounds__(256, 2)
void pred_kernel(const float* __restrict__ x, const float* __restrict__ w) {
    const int n = blockIdx.x;
    const int t = threadIdx.x;

    __shared__ float2 xs2[BB][II];   // (x,x) duplicated pairs, 8 KB
    {
        int b = t >> 2, q = t & 3;
        float4 f = reinterpret_cast<const float4*>(x + ((size_t)b * NN + n) * II)[q];
        xs2[b][4 * q + 0] = make_float2(f.x, f.x);
        xs2[b][4 * q + 1] = make_float2(f.y, f.y);
        xs2[b][4 * q + 2] = make_float2(f.z, f.z);
        xs2[b][4 * q + 3] = make_float2(f.w, f.w);
    }

    float wr[4][16];
    const float4* wp = reinterpret_cast<const float4*>(w + ((size_t)n * JO + 4 * t) * II);
#pragma unroll
    for (int q = 0; q < 4; ++q) {
#pragma unroll
        for (int c = 0; c < 4; ++c) {
            float4 f = wp[q * 4 + c];
            wr[q][4 * c + 0] = f.x; wr[q][4 * c + 1] = f.y;
            wr[q][4 * c + 2] = f.z; wr[q][4 * c + 3] = f.w;
        }
    }
    unsigned long long wp01[16], wp23[16];
#pragma unroll
    for (int i = 0; i < 16; ++i) {
        wp01[i] = pk2(wr[0][i], wr[1][i]);
        wp23[i] = pk2(wr[2][i], wr[3][i]);
    }
    __syncthreads();

    __half* outp = g_predh + (size_t)n * JO + 4 * t;
    uint32_t xbase = (uint32_t)__cvta_generic_to_shared(&xs2[0][0]);

#pragma unroll 4
    for (int b = 0; b < BB; ++b) {
        uint32_t xa = xbase + b * (II * 8);
        unsigned long long acc01 = 0ull, acc23 = 0ull;
#pragma unroll
        for (int k = 0; k < 8; ++k) {
            unsigned long long xx0, xx1;
            asm("ld.shared.v2.u64 {%0, %1}, [%2];"
                : "=l"(xx0), "=l"(xx1) : "r"(xa + k * 16));
            ffma2(acc01, xx0, wp01[2 * k]);
            ffma2(acc23, xx0, wp23[2 * k]);
            ffma2(acc01, xx1, wp01[2 * k + 1]);
            ffma2(acc23, xx1, wp23[2 * k + 1]);
        }
        float2 a01 = up2(acc01);
        float2 a23 = up2(acc23);
        __half2 b01 = __float22half2_rn(a01);
        __half2 b23 = __float22half2_rn(a23);
        uint2 st;
        st.x = *reinterpret_cast<unsigned int*>(&b01);
        st.y = *reinterpret_cast<unsigned int*>(&b23);
        *reinterpret_cast<uint2*>(outp + (size_t)b * NN * JO) = st;
    }
}

// ---------------------------------------------------------------------------
// K2: iter-0 s (uniform coupling). Pure streaming sum, no smem / no barriers.
// Grid (NCHUNK, B), 256 threads; thread t owns jo quad [4t,4t+4).
// ---------------------------------------------------------------------------
__global__ __launch_bounds__(256)
void sum0_kernel() {
    const int chunk = blockIdx.x;
    const int b = blockIdx.y;
    const int t = threadIdx.x;
    const uint2* predp = reinterpret_cast<const uint2*>(
        g_predh + ((size_t)b * NN + (size_t)chunk * CHUNK) * JO);

    float4 sacc = make_float4(0.f, 0.f, 0.f, 0.f);
#pragma unroll 8
    for (int n = 0; n < CHUNK; ++n) {
        float4 p = h4_to_f4(predp[(size_t)n * (JO / 4) + t]);
        sacc.x += p.x; sacc.y += p.y; sacc.z += p.z; sacc.w += p.w;
    }
    const float inv = 1.0f / 32.0f;
    sacc.x *= inv; sacc.y *= inv; sacc.z *= inv; sacc.w *= inv;
    reinterpret_cast<float4*>(g_partial + ((size_t)chunk * BB + b) * JO)[t] = sacc;
}

// ---------------------------------------------------------------------------
// K3: routing pass (iters 1,2). Prologue: reduce g_partial -> s, squash -> v
// (in registers; no separate squash kernel). Main loop: 8 n per round; dot
// partials go to smem (no shuffle trees); softmax warp sums 8 partials + does
// the 32-lane softmax; then c-weighted accumulation.
//   MODE 1: a = pred.v,  blog = a, softmax(a)
//   MODE 2: a = blog + pred.v,    softmax(a)
// ---------------------------------------------------------------------------
template <int MODE>
__global__ __launch_bounds__(256)
void pass_kernel() {
    const int chunk = blockIdx.x;
    const int b = blockIdx.y;
    const int t = threadIdx.x;
    const int warp = t >> 5;
    const int lane = t & 31;
    const int j = t >> 3;         // capsule of this thread's quad
    const int sub = t & 7;        // which eighth of capsule j

    __shared__ float a_part[NB][JJ][8];   // 8 KB: per-n, per-j, 8 partial dots
    __shared__ float c_buf[NB][JJ];       // 1 KB: coupling coefficients

    // ---- prologue: s = sum of partials for this b; v = squash(s) ----
    float4 sv = make_float4(0.f, 0.f, 0.f, 0.f);
#pragma unroll
    for (int k = 0; k < NCHUNK; ++k) {
        float4 p = reinterpret_cast<const float4*>(
            g_partial + ((size_t)k * BB + b) * JO)[t];
        sv.x += p.x; sv.y += p.y; sv.z += p.z; sv.w += p.w;
    }
    float sq = sv.x * sv.x + sv.y * sv.y + sv.z * sv.z + sv.w * sv.w;
    sq += __shfl_xor_sync(0xffffffffu, sq, 1);
    sq += __shfl_xor_sync(0xffffffffu, sq, 2);
    sq += __shfl_xor_sync(0xffffffffu, sq, 4);
    float scale = (sq / (1.0f + sq)) * rsqrtf(sq + 1e-8f);
    float4 vv = make_float4(sv.x * scale, sv.y * scale, sv.z * scale, sv.w * scale);

    float4 sacc = make_float4(0.f, 0.f, 0.f, 0.f);
    const uint2* predp = reinterpret_cast<const uint2*>(
        g_predh + ((size_t)b * NN + (size_t)chunk * CHUNK) * JO);

    for (int n0 = 0; n0 < CHUNK; n0 += NB) {
        float4 p[NB];
#pragma unroll
        for (int k = 0; k < NB; ++k)
            p[k] = h4_to_f4(predp[(size_t)(n0 + k) * (JO / 4) + t]);

        // dot partials -> smem (contiguous per warp: conflict-free)
#pragma unroll
        for (int k = 0; k < NB; ++k)
            a_part[k][j][sub] =
                p[k].x * vv.x + p[k].y * vv.y + p[k].z * vv.z + p[k].w * vv.w;
        __syncthreads();

        {   // warp k handles n0+k: finish dot, blog, softmax over 32 capsules
            const int k = warp;
            const int n = chunk * CHUNK + n0 + k;
            float4 q0 = *reinterpret_cast<const float4*>(&a_part[k][lane][0]);
            float4 q1 = *reinterpret_cast<const float4*>(&a_part[k][lane][4]);
            float a = ((q0.x + q0.y) + (q0.z + q0.w)) +
                      ((q1.x + q1.y) + (q1.z + q1.w));
            size_t bidx = ((size_t)b * NN + n) * JJ + lane;
            if (MODE == 2) a += g_blog[bidx];
            else           g_blog[bidx] = a;     // b1 = agreement (b0 = 0)
            float m = a;
#pragma unroll
            for (int s = 16; s > 0; s >>= 1)
                m = fmaxf(m, __shfl_xor_sync(0xffffffffu, m, s));
            float e = __expf(a - m);
            float ssum = e;
#pragma unroll
            for (int s = 16; s > 0; s >>= 1)
                ssum += __shfl_xor_sync(0xffffffffu, ssum, s);
            c_buf[k][lane] = e / ssum;
        }
        __syncthreads();

#pragma unroll
        for (int k = 0; k < NB; ++k) {
            float c = c_buf[k][j];
            sacc.x = fmaf(c, p[k].x, sacc.x);
            sacc.y = fmaf(c, p[k].y, sacc.y);
            sacc.z = fmaf(c, p[k].z, sacc.z);
            sacc.w = fmaf(c, p[k].w, sacc.w);
        }
    }
    reinterpret_cast<float4*>(g_partial + ((size_t)chunk * BB + b) * JO)[t] = sacc;
}

// ---------------------------------------------------------------------------
// K4: final reduce + squash -> d_out. One block per b, thread t = jo.
// ---------------------------------------------------------------------------
__global__ __launch_bounds__(1024)
void squash_kernel(float* __restrict__ out) {
    const int b = blockIdx.x;
    const int t = threadIdx.x;
    float s = 0.f;
#pragma unroll
    for (int k = 0; k < NCHUNK; ++k)
        s += g_partial[((size_t)k * BB + b) * JO + t];
    float sq = s * s;
#pragma unroll
    for (int m = 16; m > 0; m >>= 1)
        sq += __shfl_xor_sync(0xffffffffu, sq, m);
    float scale = (sq / (1.0f + sq)) * rsqrtf(sq + 1e-8f);
    out[b * JO + t] = s * scale;
}

// ---------------------------------------------------------------------------
extern "C" void kernel_launch(void* const* d_in, const int* in_sizes, int n_in,
                              void* d_out, int out_size) {
    const float* x = (const float*)d_in[0];   // [64, 2048, 16] f32
    const float* w = (const float*)d_in[1];   // [2048, 32, 32, 16] f32
    float* out = (float*)d_out;               // [64, 32, 32] f32

    dim3 pg(NCHUNK, BB);
    pred_kernel<<<NN, 256>>>(x, w);
    sum0_kernel<<<pg, 256>>>();               // iter 0: uniform c -> s0 partials
    pass_kernel<1><<<pg, 256>>>();            // v0 (prologue) -> b1 -> c1 -> s1
    pass_kernel<2><<<pg, 256>>>();            // v1 (prologue) -> b2 -> c2 -> s2
    squash_kernel<<<BB, 1024>>>(out);         // v2 -> output
}